// round 9
// baseline (speedup 1.0000x reference)
#include <cuda_runtime.h>
#include <cstdint>

static constexpr int   kVocab   = 128000;
static constexpr int   kTopK    = 50;
static constexpr float kTopP    = 0.9f;
static constexpr float kNeg     = -1000000000.0f;
static constexpr int   kMaxRows = 256;
static constexpr int   kSlices  = 8;
static constexpr int   kSliceF  = kVocab / kSlices;   // 16000 floats per scan block
static constexpr int   kSliceF4 = kSliceF / 4;        // 4000 float4
static constexpr int   kSegCap  = 512;                // per-slice candidate cap
static constexpr int   kRowCap  = kSlices * kSegCap;  // 4096
static constexpr int   kFillBlocks = 2048;
static constexpr int   kWCap    = 64;                 // fallback per-warp cap

// Global scratch (device globals — no allocation).
__device__ unsigned long long g_cand[kMaxRows * kRowCap];   // 8 MB
__device__ int   g_cnt[kMaxRows * kSlices];
__device__ float g_thr[kMaxRows * kSlices];

// Order-preserving float -> uint32 key (monotone increasing, >0 for any float).
__device__ __forceinline__ unsigned f2key(float f) {
    unsigned b = __float_as_uint(f);
    return (b & 0x80000000u) ? ~b : (b | 0x80000000u);
}
__device__ __forceinline__ float key2f(unsigned k) {
    unsigned b = (k & 0x80000000u) ? (k & 0x7FFFFFFFu) : ~k;
    return __uint_as_float(b);
}
__device__ __forceinline__ unsigned long long shfl_xor64(unsigned long long v, int j) {
    unsigned lo = __shfl_xor_sync(0xffffffffu, (unsigned)v, j);
    unsigned hi = __shfl_xor_sync(0xffffffffu, (unsigned)(v >> 32), j);
    return ((unsigned long long)hi << 32) | lo;
}
__device__ __forceinline__ float fmax4(float4 a) {
    return fmaxf(fmaxf(a.x, a.y), fmaxf(a.z, a.w));
}

// ---------------------------------------------------------------------------
// K1: fill blocks (0..2047) NEG-fill output; scan blocks (2048..) stream one
// 16000-float slice each and emit candidates to global segments.
// ---------------------------------------------------------------------------
__global__ void __launch_bounds__(256)
stream_kernel(const float* __restrict__ in, float* __restrict__ out, int rows) {
    const int tid = threadIdx.x;

    if (blockIdx.x < kFillBlocks) {
        float4* out4 = reinterpret_cast<float4*>(out);
        const int n4 = rows * (kVocab / 4);
        const float4 neg4 = make_float4(kNeg, kNeg, kNeg, kNeg);
        const int stride = kFillBlocks * 256;
        int i = blockIdx.x * 256 + tid;
#pragma unroll 4
        for (; i < n4; i += stride)
            __stcs(&out4[i], neg4);
        return;
    }

    const int sb    = blockIdx.x - kFillBlocks;   // 0 .. rows*8-1
    const int row   = sb >> 3;
    const int slice = sb & 7;
    const float* base = in + (long long)row * kVocab + slice * kSliceF;
    const int lane = tid & 31, wid = tid >> 5;

    __shared__ float s_wm8[8];
    __shared__ float s_Ts;
    __shared__ int   s_cnt;
    __shared__ unsigned long long s_c[kSegCap];

    // 512 strided samples -> 8 warp maxima -> threshold = 2nd largest warp max.
    float sv = fmaxf(__ldg(&base[tid * 31]), __ldg(&base[(256 + tid) * 31]));
#pragma unroll
    for (int o = 16; o > 0; o >>= 1)
        sv = fmaxf(sv, __shfl_xor_sync(0xffffffffu, sv, o));
    if (lane == 0) s_wm8[wid] = sv;
    if (tid == 0) s_cnt = 0;
    __syncthreads();
    if (tid == 0) {
        float m1 = -3.4e38f, m2 = -3.4e38f;
#pragma unroll
        for (int j = 0; j < 8; ++j) {
            float v = s_wm8[j];
            if (v > m1) { m2 = m1; m1 = v; } else if (v > m2) m2 = v;
        }
        s_Ts = m2;
    }
    __syncthreads();
    const float T = s_Ts;

#define PUSHK(val, gi)                                                         \
    if ((val) > T) { int p = atomicAdd(&s_cnt, 1);                             \
        if (p < kSegCap)                                                       \
            s_c[p] = ((unsigned long long)f2key(val) << 32) | (unsigned)(gi); }

    const float4* b4 = reinterpret_cast<const float4*>(base);
    for (int i0 = tid; i0 < kSliceF4; i0 += 1024) {
        const int i1 = i0 + 256, i2 = i0 + 512, i3 = i0 + 768;
        const bool h1 = i1 < kSliceF4, h2 = i2 < kSliceF4, h3 = i3 < kSliceF4;
        float4 a = __ldcs(&b4[i0]);
        float4 b, c, d;
        if (h1) b = __ldcs(&b4[i1]);
        if (h2) c = __ldcs(&b4[i2]);
        if (h3) d = __ldcs(&b4[i3]);
        if (fmax4(a) > T) {
            int g = slice * kSliceF + 4 * i0;
            PUSHK(a.x, g) PUSHK(a.y, g + 1) PUSHK(a.z, g + 2) PUSHK(a.w, g + 3)
        }
        if (h1 && fmax4(b) > T) {
            int g = slice * kSliceF + 4 * i1;
            PUSHK(b.x, g) PUSHK(b.y, g + 1) PUSHK(b.z, g + 2) PUSHK(b.w, g + 3)
        }
        if (h2 && fmax4(c) > T) {
            int g = slice * kSliceF + 4 * i2;
            PUSHK(c.x, g) PUSHK(c.y, g + 1) PUSHK(c.z, g + 2) PUSHK(c.w, g + 3)
        }
        if (h3 && fmax4(d) > T) {
            int g = slice * kSliceF + 4 * i3;
            PUSHK(d.x, g) PUSHK(d.y, g + 1) PUSHK(d.z, g + 2) PUSHK(d.w, g + 3)
        }
    }
#undef PUSHK
    __syncthreads();

    const int raw = s_cnt;
    const int cnt = raw < kSegCap ? raw : kSegCap;
    unsigned long long* seg = &g_cand[((long long)row << 12) + (slice << 9)];
    for (int e = tid; e < cnt; e += 256)
        seg[e] = s_c[e];
    if (tid == 0) { g_cnt[sb] = raw; g_thr[sb] = T; }
}

// ---------------------------------------------------------------------------
// Shared descending sort (zero-pads [total, npad)); requires total <= 4096.
// Must be called by all 1024 threads (uniform).
// ---------------------------------------------------------------------------
__device__ void sort_desc(unsigned long long* s_data, int total, int tid) {
    int npad = 64;
    while (npad < total) npad <<= 1;
    for (int i = total + tid; i < npad; i += 1024) s_data[i] = 0ull;
    __syncthreads();

    if (npad <= 1024) {
        const bool act = tid < npad;
        unsigned long long v = act ? s_data[tid] : 0ull;
        for (int k = 2; k <= npad; k <<= 1) {
            int j = k >> 1;
            for (; j >= 32; j >>= 1) {
                __syncthreads();
                if (act) s_data[tid] = v;
                __syncthreads();
                if (act) {
                    unsigned long long u = s_data[tid ^ j];
                    bool takeMax = (((tid & k) == 0) == ((tid & j) == 0));
                    v = takeMax ? (v > u ? v : u) : (v < u ? v : u);
                }
            }
            for (; j > 0; j >>= 1) {
                unsigned long long u = shfl_xor64(v, j);
                bool takeMax = (((tid & k) == 0) == ((tid & j) == 0));
                v = takeMax ? (v > u ? v : u) : (v < u ? v : u);
            }
        }
        __syncthreads();
        if (act) s_data[tid] = v;
        __syncthreads();
    } else {
        for (int k = 2; k <= npad; k <<= 1) {
            for (int j = k >> 1; j > 0; j >>= 1) {
#pragma unroll 1
                for (int i = tid; i < npad; i += 1024) {
                    int p = i ^ j;
                    if (p > i) {
                        unsigned long long a = s_data[i], b = s_data[p];
                        bool desc = ((i & k) == 0);
                        if (desc ? (a < b) : (a > b)) { s_data[i] = b; s_data[p] = a; }
                    }
                }
                __syncthreads();
            }
        }
    }
}

// ---------------------------------------------------------------------------
// K2: per-row gather + validity check + sort + top-p + scatter.
// ---------------------------------------------------------------------------
__global__ void __launch_bounds__(1024)
sort_scatter_kernel(const float* __restrict__ in, float* __restrict__ out) {
    extern __shared__ __align__(16) unsigned long long s_data[];  // kRowCap
    __shared__ int   s_pref[kSlices];
    __shared__ int   s_cnt8[kSlices];
    __shared__ float s_Tmax;
    __shared__ int   s_total, s_flag, s_ovf;
    __shared__ float s_wm[32];
    __shared__ int   s_wcnt[32], s_woff[32];
    __shared__ float s_ex[kTopK];
    __shared__ int   s_k;

    const int row = blockIdx.x;
    const int tid = threadIdx.x, lane = tid & 31, wid = tid >> 5;
    const float* rin  = in  + (long long)row * kVocab;
    float*       rout = out + (long long)row * kVocab;

    if (tid < kSlices) s_cnt8[tid] = g_cnt[row * kSlices + tid];
    __syncthreads();
    if (tid == 0) {
        int tot = 0, ovf = 0; float tmx = -3.4e38f;
#pragma unroll
        for (int j = 0; j < kSlices; ++j) {
            int c = s_cnt8[j];
            if (c > kSegCap) { ovf = 1; c = kSegCap; }
            s_pref[j] = tot; tot += c;
            float t = g_thr[row * kSlices + j];
            if (t > tmx) tmx = t;
        }
        s_total = tot; s_ovf = ovf; s_Tmax = tmx;
    }
    __syncthreads();
    int total = s_total;
    const bool tryPrimary = (!s_ovf && total >= kTopK);

    if (tryPrimary && wid < kSlices) {
        const int c = min(s_cnt8[wid], kSegCap);
        const int off = s_pref[wid];
        const unsigned long long* seg = &g_cand[((long long)row << 12) + (wid << 9)];
        for (int e = lane; e < c; e += 32)
            s_data[off + e] = seg[e];
    }
    __syncthreads();

    bool valid = false;
    if (tryPrimary) {
        sort_desc(s_data, total, tid);
        // Kept-set guarantee: >= kTopK candidates strictly above max slice threshold.
        if (tid == 0)
            s_flag = (key2f((unsigned)(s_data[kTopK - 1] >> 32)) > s_Tmax) ? 1 : 0;
        __syncthreads();
        valid = (s_flag != 0);
    }

    if (!valid) {
        // ---- rare fallback: full-row rescan with sampled threshold ladder ----
        float sv = __ldg(&rin[tid * (kVocab / 1024)]);
#pragma unroll
        for (int o = 16; o > 0; o >>= 1)
            sv = fmaxf(sv, __shfl_xor_sync(0xffffffffu, sv, o));
        if (lane == 0) s_wm[wid] = sv;
        __syncthreads();
        if (wid == 0) {
            float x = s_wm[lane];
#pragma unroll
            for (int k = 2; k <= 32; k <<= 1) {
#pragma unroll
                for (int j = k >> 1; j > 0; j >>= 1) {
                    float y     = __shfl_xor_sync(0xffffffffu, x, j);
                    bool  up    = ((lane & k) == 0);
                    bool  lower = ((lane & j) == 0);
                    x = (up == lower) ? fminf(x, y) : fmaxf(x, y);
                }
            }
            s_wm[lane] = x;  // ascending
        }
        __syncthreads();

        unsigned long long* seg = s_data + 2048;   // per-warp segments region
        const float4* rin4 = reinterpret_cast<const float4*>(rin);
        int rank = 5;
        for (int attempt = 0; attempt < 6; ++attempt) {
            if (tid < 32) s_wcnt[tid] = 0;
            __syncthreads();
            const float T = s_wm[31 - rank];
            for (int i = tid; i < kVocab / 4; i += 1024) {
                float4 a = __ldg(&rin4[i]);
                if (fmax4(a) > T) {
#define FPUSH(val, gi)                                                          \
    if ((val) > T) { int p = atomicAdd(&s_wcnt[wid], 1);                        \
        if (p < kWCap)                                                          \
            seg[wid * kWCap + p] =                                              \
                ((unsigned long long)f2key(val) << 32) | (unsigned)(gi); }
                    FPUSH(a.x, 4 * i) FPUSH(a.y, 4 * i + 1)
                    FPUSH(a.z, 4 * i + 2) FPUSH(a.w, 4 * i + 3)
#undef FPUSH
                }
            }
            __syncthreads();
            if (wid == 0) {
                int c = s_wcnt[lane];
                int ov = __any_sync(0xffffffffu, c > kWCap) ? 1 : 0;
                int t = c;
#pragma unroll
                for (int o = 16; o > 0; o >>= 1) t += __shfl_xor_sync(0xffffffffu, t, o);
                if (lane == 0) { s_total = t; s_ovf = ov; }
            }
            __syncthreads();
            const int tot = s_total, ov = s_ovf;
            if (tot >= kTopK && !ov) break;
            rank = ov ? (rank >> 1) : (rank < 31 ? rank * 2 + 1 : 31);
            __syncthreads();
        }
        // compact per-warp segments into s_data[0..total)
        if (wid == 0) {
            int c = min(s_wcnt[lane], kWCap);
            int x = c;
#pragma unroll
            for (int o = 1; o < 32; o <<= 1) {
                int y = __shfl_up_sync(0xffffffffu, x, o);
                if (lane >= o) x += y;
            }
            s_woff[lane] = x - c;
            if (lane == 31) s_total = x;  // inclusive total of capped counts
        }
        __syncthreads();
        {
            const int c = min(s_wcnt[wid], kWCap);
            const int off = s_woff[wid];
            for (int e = lane; e < c; e += 32)
                s_data[off + e] = seg[wid * kWCap + e];
        }
        __syncthreads();
        total = s_total;
        sort_desc(s_data, total, tid);
    }

    // ---------------- top-p epilogue ----------------
    const int lim = (total < kTopK) ? total : kTopK;
    if (wid == 0) {
        float m = key2f((unsigned)(s_data[0] >> 32));
#pragma unroll
        for (int j = lane; j < kTopK; j += 32)
            if (j < lim)
                s_ex[j] = expf(key2f((unsigned)(s_data[j] >> 32)) - m);
    }
    __syncthreads();
    if (tid == 0) {
        int kk = 0;
        if (lim > 0) {
            float Z = 0.f;
            for (int j = 0; j < lim; ++j) Z += s_ex[j];
            const float invZ = 1.0f / Z;
            float cum = 0.f;
            for (int j = 0; j < lim; ++j) {
                if (j > 0 && cum > kTopP) break;
                kk = j + 1;
                cum += s_ex[j] * invZ;
            }
        }
        s_k = kk;
    }
    __syncthreads();

    if (tid < s_k) {
        unsigned long long c = s_data[tid];
        rout[(int)(c & 0xFFFFFFFFu)] = key2f((unsigned)(c >> 32));
    }
}

extern "C" void kernel_launch(void* const* d_in, const int* in_sizes, int n_in,
                              void* d_out, int out_size) {
    const float* in = (const float*)d_in[0];
    float* out = (float*)d_out;
    int rows = in_sizes[0] / kVocab;
    stream_kernel<<<kFillBlocks + rows * kSlices, 256>>>(in, out, rows);
    sort_scatter_kernel<<<rows, 1024, kRowCap * sizeof(unsigned long long)>>>(in, out);
}

// round 10
// speedup vs baseline: 1.1513x; 1.1513x over previous
#include <cuda_runtime.h>
#include <cstdint>

static constexpr int   kVocab   = 128000;
static constexpr int   kTopK    = 50;
static constexpr float kTopP    = 0.9f;
static constexpr float kNeg     = -1000000000.0f;
static constexpr int   kMaxRows = 256;
static constexpr int   kSlices  = 8;
static constexpr int   kSliceF  = kVocab / kSlices;   // 16000 floats per scan block
static constexpr int   kSliceF4 = kSliceF / 4;        // 4000 float4
static constexpr int   kSegCap  = 512;                // per-slice candidate cap
static constexpr int   kRowCap  = kSlices * kSegCap;  // 4096
static constexpr int   kFillBlocks = 2048;
static constexpr int   kWCap    = 64;                 // fallback per-warp cap

// Global scratch (device globals — no allocation).
__device__ unsigned long long g_cand[kMaxRows * kRowCap];   // 8 MB
__device__ int   g_cnt[kMaxRows * kSlices];
__device__ float g_rowthr[kMaxRows];

// Order-preserving float -> uint32 key (monotone increasing, >0 for any float).
__device__ __forceinline__ unsigned f2key(float f) {
    unsigned b = __float_as_uint(f);
    return (b & 0x80000000u) ? ~b : (b | 0x80000000u);
}
__device__ __forceinline__ float key2f(unsigned k) {
    unsigned b = (k & 0x80000000u) ? (k & 0x7FFFFFFFu) : ~k;
    return __uint_as_float(b);
}
__device__ __forceinline__ unsigned long long shfl_xor64(unsigned long long v, int j) {
    unsigned lo = __shfl_xor_sync(0xffffffffu, (unsigned)v, j);
    unsigned hi = __shfl_xor_sync(0xffffffffu, (unsigned)(v >> 32), j);
    return ((unsigned long long)hi << 32) | lo;
}
__device__ __forceinline__ float fmax4(float4 a) {
    return fmaxf(fmaxf(a.x, a.y), fmaxf(a.z, a.w));
}

// ---------------------------------------------------------------------------
// K0: per-row threshold from 1024 strided samples (rank-5 of sorted warp maxes
// -> expected exceedance ~750 over 128000, P(<50) ~ 1e-8).
// ---------------------------------------------------------------------------
__global__ void __launch_bounds__(1024)
rowthr_kernel(const float* __restrict__ in) {
    __shared__ float s_wm[32];
    const int row = blockIdx.x;
    const int tid = threadIdx.x, lane = tid & 31, wid = tid >> 5;
    const float* rin = in + (long long)row * kVocab;

    float sv = __ldg(&rin[tid * (kVocab / 1024)]);
#pragma unroll
    for (int o = 16; o > 0; o >>= 1)
        sv = fmaxf(sv, __shfl_xor_sync(0xffffffffu, sv, o));
    if (lane == 0) s_wm[wid] = sv;
    __syncthreads();
    if (wid == 0) {
        float x = s_wm[lane];
#pragma unroll
        for (int k = 2; k <= 32; k <<= 1) {
#pragma unroll
            for (int j = k >> 1; j > 0; j >>= 1) {
                float y     = __shfl_xor_sync(0xffffffffu, x, j);
                bool  up    = ((lane & k) == 0);
                bool  lower = ((lane & j) == 0);
                x = (up == lower) ? fminf(x, y) : fmaxf(x, y);
            }
        }
        if (lane == 31 - 5) g_rowthr[row] = x;  // 6th-largest warp max
    }
}

// ---------------------------------------------------------------------------
// K1: fill blocks (0..2047) NEG-fill output; scan blocks (2048..) stream one
// 16000-float slice each with the shared row threshold.
// ---------------------------------------------------------------------------
__global__ void __launch_bounds__(256)
stream_kernel(const float* __restrict__ in, float* __restrict__ out, int rows) {
    const int tid = threadIdx.x;

    if (blockIdx.x < kFillBlocks) {
        float4* out4 = reinterpret_cast<float4*>(out);
        const int n4 = rows * (kVocab / 4);
        const float4 neg4 = make_float4(kNeg, kNeg, kNeg, kNeg);
        const int stride = kFillBlocks * 256;
        int i = blockIdx.x * 256 + tid;
#pragma unroll 4
        for (; i < n4; i += stride)
            __stcs(&out4[i], neg4);
        return;
    }

    const int sb    = blockIdx.x - kFillBlocks;   // 0 .. rows*8-1
    const int row   = sb >> 3;
    const int slice = sb & 7;
    const float* base = in + (long long)row * kVocab + slice * kSliceF;

    __shared__ int s_cnt;
    __shared__ unsigned long long s_c[kSegCap];
    if (tid == 0) s_cnt = 0;
    __syncthreads();
    const float T = g_rowthr[row];

#define PUSHK(val, gi)                                                         \
    if ((val) > T) { int p = atomicAdd(&s_cnt, 1);                             \
        if (p < kSegCap)                                                       \
            s_c[p] = ((unsigned long long)f2key(val) << 32) | (unsigned)(gi); }

    const float4* b4 = reinterpret_cast<const float4*>(base);
    for (int i0 = tid; i0 < kSliceF4; i0 += 1024) {
        const int i1 = i0 + 256, i2 = i0 + 512, i3 = i0 + 768;
        const bool h1 = i1 < kSliceF4, h2 = i2 < kSliceF4, h3 = i3 < kSliceF4;
        float4 a = __ldcs(&b4[i0]);
        float4 b, c, d;
        if (h1) b = __ldcs(&b4[i1]);
        if (h2) c = __ldcs(&b4[i2]);
        if (h3) d = __ldcs(&b4[i3]);
        if (fmax4(a) > T) {
            int g = slice * kSliceF + 4 * i0;
            PUSHK(a.x, g) PUSHK(a.y, g + 1) PUSHK(a.z, g + 2) PUSHK(a.w, g + 3)
        }
        if (h1 && fmax4(b) > T) {
            int g = slice * kSliceF + 4 * i1;
            PUSHK(b.x, g) PUSHK(b.y, g + 1) PUSHK(b.z, g + 2) PUSHK(b.w, g + 3)
        }
        if (h2 && fmax4(c) > T) {
            int g = slice * kSliceF + 4 * i2;
            PUSHK(c.x, g) PUSHK(c.y, g + 1) PUSHK(c.z, g + 2) PUSHK(c.w, g + 3)
        }
        if (h3 && fmax4(d) > T) {
            int g = slice * kSliceF + 4 * i3;
            PUSHK(d.x, g) PUSHK(d.y, g + 1) PUSHK(d.z, g + 2) PUSHK(d.w, g + 3)
        }
    }
#undef PUSHK
    __syncthreads();

    const int raw = s_cnt;
    const int cnt = raw < kSegCap ? raw : kSegCap;
    unsigned long long* seg = &g_cand[((long long)row << 12) + (slice << 9)];
    for (int e = tid; e < cnt; e += 256)
        seg[e] = s_c[e];
    if (tid == 0) g_cnt[sb] = raw;
}

// ---------------------------------------------------------------------------
// Shared descending sort (zero-pads [total, npad)); requires total <= 4096.
// Must be called by all 1024 threads (uniform).
// ---------------------------------------------------------------------------
__device__ void sort_desc(unsigned long long* s_data, int total, int tid) {
    int npad = 64;
    while (npad < total) npad <<= 1;
    for (int i = total + tid; i < npad; i += 1024) s_data[i] = 0ull;
    __syncthreads();

    if (npad <= 1024) {
        const bool act = tid < npad;
        unsigned long long v = act ? s_data[tid] : 0ull;
        for (int k = 2; k <= npad; k <<= 1) {
            int j = k >> 1;
            for (; j >= 32; j >>= 1) {
                __syncthreads();
                if (act) s_data[tid] = v;
                __syncthreads();
                if (act) {
                    unsigned long long u = s_data[tid ^ j];
                    bool takeMax = (((tid & k) == 0) == ((tid & j) == 0));
                    v = takeMax ? (v > u ? v : u) : (v < u ? v : u);
                }
            }
            for (; j > 0; j >>= 1) {
                unsigned long long u = shfl_xor64(v, j);
                bool takeMax = (((tid & k) == 0) == ((tid & j) == 0));
                v = takeMax ? (v > u ? v : u) : (v < u ? v : u);
            }
        }
        __syncthreads();
        if (act) s_data[tid] = v;
        __syncthreads();
    } else {
        for (int k = 2; k <= npad; k <<= 1) {
            for (int j = k >> 1; j > 0; j >>= 1) {
#pragma unroll 1
                for (int i = tid; i < npad; i += 1024) {
                    int p = i ^ j;
                    if (p > i) {
                        unsigned long long a = s_data[i], b = s_data[p];
                        bool desc = ((i & k) == 0);
                        if (desc ? (a < b) : (a > b)) { s_data[i] = b; s_data[p] = a; }
                    }
                }
                __syncthreads();
            }
        }
    }
}

// ---------------------------------------------------------------------------
// K2: per-row gather + sort + top-p + scatter (fallback ~never taken).
// ---------------------------------------------------------------------------
__global__ void __launch_bounds__(1024)
sort_scatter_kernel(const float* __restrict__ in, float* __restrict__ out) {
    extern __shared__ __align__(16) unsigned long long s_data[];  // kRowCap
    __shared__ int   s_pref[kSlices];
    __shared__ int   s_cnt8[kSlices];
    __shared__ int   s_total, s_ovf;
    __shared__ float s_wm[32];
    __shared__ int   s_wcnt[32], s_woff[32];
    __shared__ float s_ex[kTopK];
    __shared__ int   s_k;

    const int row = blockIdx.x;
    const int tid = threadIdx.x, lane = tid & 31, wid = tid >> 5;
    const float* rin  = in  + (long long)row * kVocab;
    float*       rout = out + (long long)row * kVocab;

    if (tid < kSlices) s_cnt8[tid] = g_cnt[row * kSlices + tid];
    __syncthreads();
    if (tid == 0) {
        int tot = 0, ovf = 0;
#pragma unroll
        for (int j = 0; j < kSlices; ++j) {
            int c = s_cnt8[j];
            if (c > kSegCap) { ovf = 1; c = kSegCap; }
            s_pref[j] = tot; tot += c;
        }
        s_total = tot; s_ovf = ovf;
    }
    __syncthreads();
    int total = s_total;
    // Single row threshold: total >= 50 with no overflow guarantees the top-50
    // is contained in the candidate set.
    const bool valid = (!s_ovf && total >= kTopK);

    if (valid) {
        if (wid < kSlices) {
            const int c = min(s_cnt8[wid], kSegCap);
            const int off = s_pref[wid];
            const unsigned long long* seg = &g_cand[((long long)row << 12) + (wid << 9)];
            for (int e = lane; e < c; e += 32)
                s_data[off + e] = seg[e];
        }
        __syncthreads();
        sort_desc(s_data, total, tid);
    } else {
        // ---- rare fallback: full-row rescan with sampled threshold ladder ----
        float sv = __ldg(&rin[tid * (kVocab / 1024)]);
#pragma unroll
        for (int o = 16; o > 0; o >>= 1)
            sv = fmaxf(sv, __shfl_xor_sync(0xffffffffu, sv, o));
        if (lane == 0) s_wm[wid] = sv;
        __syncthreads();
        if (wid == 0) {
            float x = s_wm[lane];
#pragma unroll
            for (int k = 2; k <= 32; k <<= 1) {
#pragma unroll
                for (int j = k >> 1; j > 0; j >>= 1) {
                    float y     = __shfl_xor_sync(0xffffffffu, x, j);
                    bool  up    = ((lane & k) == 0);
                    bool  lower = ((lane & j) == 0);
                    x = (up == lower) ? fminf(x, y) : fmaxf(x, y);
                }
            }
            s_wm[lane] = x;  // ascending
        }
        __syncthreads();

        unsigned long long* seg = s_data + 2048;   // per-warp segments region
        const float4* rin4 = reinterpret_cast<const float4*>(rin);
        int rank = 7;
        for (int attempt = 0; attempt < 6; ++attempt) {
            if (tid < 32) s_wcnt[tid] = 0;
            __syncthreads();
            const float T = s_wm[31 - rank];
            for (int i = tid; i < kVocab / 4; i += 1024) {
                float4 a = __ldg(&rin4[i]);
                if (fmax4(a) > T) {
#define FPUSH(val, gi)                                                          \
    if ((val) > T) { int p = atomicAdd(&s_wcnt[wid], 1);                        \
        if (p < kWCap)                                                          \
            seg[wid * kWCap + p] =                                              \
                ((unsigned long long)f2key(val) << 32) | (unsigned)(gi); }
                    FPUSH(a.x, 4 * i) FPUSH(a.y, 4 * i + 1)
                    FPUSH(a.z, 4 * i + 2) FPUSH(a.w, 4 * i + 3)
#undef FPUSH
                }
            }
            __syncthreads();
            if (wid == 0) {
                int c = s_wcnt[lane];
                int ov = __any_sync(0xffffffffu, c > kWCap) ? 1 : 0;
                int t = c;
#pragma unroll
                for (int o = 16; o > 0; o >>= 1) t += __shfl_xor_sync(0xffffffffu, t, o);
                if (lane == 0) { s_total = t; s_ovf = ov; }
            }
            __syncthreads();
            const int tot = s_total, ov = s_ovf;
            if (tot >= kTopK && !ov) break;
            rank = ov ? (rank >> 1) : (rank < 31 ? rank * 2 + 1 : 31);
            __syncthreads();
        }
        // compact per-warp segments into s_data[0..total)
        if (wid == 0) {
            int c = min(s_wcnt[lane], kWCap);
            int x = c;
#pragma unroll
            for (int o = 1; o < 32; o <<= 1) {
                int y = __shfl_up_sync(0xffffffffu, x, o);
                if (lane >= o) x += y;
            }
            s_woff[lane] = x - c;
            if (lane == 31) s_total = x;  // total of capped counts
        }
        __syncthreads();
        {
            const int c = min(s_wcnt[wid], kWCap);
            const int off = s_woff[wid];
            for (int e = lane; e < c; e += 32)
                s_data[off + e] = seg[wid * kWCap + e];
        }
        __syncthreads();
        total = s_total;
        sort_desc(s_data, total, tid);
    }

    // ---------------- top-p epilogue ----------------
    const int lim = (total < kTopK) ? total : kTopK;
    if (wid == 0) {
        float m = key2f((unsigned)(s_data[0] >> 32));
#pragma unroll
        for (int j = lane; j < kTopK; j += 32)
            if (j < lim)
                s_ex[j] = expf(key2f((unsigned)(s_data[j] >> 32)) - m);
    }
    __syncthreads();
    if (tid == 0) {
        int kk = 0;
        if (lim > 0) {
            float Z = 0.f;
            for (int j = 0; j < lim; ++j) Z += s_ex[j];
            const float invZ = 1.0f / Z;
            float cum = 0.f;
            for (int j = 0; j < lim; ++j) {
                if (j > 0 && cum > kTopP) break;
                kk = j + 1;
                cum += s_ex[j] * invZ;
            }
        }
        s_k = kk;
    }
    __syncthreads();

    if (tid < s_k) {
        unsigned long long c = s_data[tid];
        rout[(int)(c & 0xFFFFFFFFu)] = key2f((unsigned)(c >> 32));
    }
}

extern "C" void kernel_launch(void* const* d_in, const int* in_sizes, int n_in,
                              void* d_out, int out_size) {
    const float* in = (const float*)d_in[0];
    float* out = (float*)d_out;
    int rows = in_sizes[0] / kVocab;
    rowthr_kernel<<<rows, 1024>>>(in);
    stream_kernel<<<kFillBlocks + rows * kSlices, 256>>>(in, out, rows);
    sort_scatter_kernel<<<rows, 1024, kRowCap * sizeof(unsigned long long)>>>(in, out);
}

// round 11
// speedup vs baseline: 2.0176x; 1.7525x over previous
#include <cuda_runtime.h>
#include <cstdint>

static constexpr int   kVocab   = 128000;
static constexpr int   kTopK    = 50;
static constexpr float kTopP    = 0.9f;
static constexpr float kNeg     = -1000000000.0f;
static constexpr float kFixedT  = 3.0f;   // guess for N(0,1) logits; verified in K2
static constexpr int   kMaxRows = 256;
static constexpr int   kSlices  = 8;
static constexpr int   kSliceF  = kVocab / kSlices;   // 16000 floats per scan block
static constexpr int   kSliceF4 = kSliceF / 4;        // 4000 float4
static constexpr int   kSegCap  = 512;                // per-slice candidate cap
static constexpr int   kRowCap  = kSlices * kSegCap;  // 4096 (also smem sort area)
static constexpr int   kFillBlocks = 2048;
static constexpr int   kWCap    = 64;                 // fallback per-warp cap

// Global scratch (device globals — no allocation).
__device__ unsigned long long g_cand[kMaxRows * kRowCap];   // 8 MB
__device__ int g_cnt[kMaxRows * kSlices];

// Order-preserving float -> uint32 key (monotone increasing, >0 for any float).
__device__ __forceinline__ unsigned f2key(float f) {
    unsigned b = __float_as_uint(f);
    return (b & 0x80000000u) ? ~b : (b | 0x80000000u);
}
__device__ __forceinline__ float key2f(unsigned k) {
    unsigned b = (k & 0x80000000u) ? (k & 0x7FFFFFFFu) : ~k;
    return __uint_as_float(b);
}
__device__ __forceinline__ unsigned long long shfl_xor64(unsigned long long v, int j) {
    unsigned lo = __shfl_xor_sync(0xffffffffu, (unsigned)v, j);
    unsigned hi = __shfl_xor_sync(0xffffffffu, (unsigned)(v >> 32), j);
    return ((unsigned long long)hi << 32) | lo;
}
__device__ __forceinline__ float fmax4(float4 a) {
    return fmaxf(fmaxf(a.x, a.y), fmaxf(a.z, a.w));
}

// ---------------------------------------------------------------------------
// K1: fill blocks (0..2047) NEG-fill output; scan blocks (2048..) stream one
// 16000-float slice each with the fixed threshold.
// ---------------------------------------------------------------------------
__global__ void __launch_bounds__(256)
stream_kernel(const float* __restrict__ in, float* __restrict__ out, int rows) {
    const int tid = threadIdx.x;

    if (blockIdx.x < kFillBlocks) {
        float4* out4 = reinterpret_cast<float4*>(out);
        const int n4 = rows * (kVocab / 4);
        const float4 neg4 = make_float4(kNeg, kNeg, kNeg, kNeg);
        const int stride = kFillBlocks * 256;
        int i = blockIdx.x * 256 + tid;
#pragma unroll 4
        for (; i < n4; i += stride)
            __stcs(&out4[i], neg4);
        return;
    }

    const int sb    = blockIdx.x - kFillBlocks;   // 0 .. rows*8-1
    const int row   = sb >> 3;
    const int slice = sb & 7;
    const float* base = in + (long long)row * kVocab + slice * kSliceF;

    __shared__ int s_cnt;
    __shared__ unsigned long long s_c[kSegCap];
    if (tid == 0) s_cnt = 0;
    __syncthreads();
    const float T = kFixedT;

#define PUSHK(val, gi)                                                         \
    if ((val) > T) { int p = atomicAdd(&s_cnt, 1);                             \
        if (p < kSegCap)                                                       \
            s_c[p] = ((unsigned long long)f2key(val) << 32) | (unsigned)(gi); }

    const float4* b4 = reinterpret_cast<const float4*>(base);
    for (int i0 = tid; i0 < kSliceF4; i0 += 1024) {
        const int i1 = i0 + 256, i2 = i0 + 512, i3 = i0 + 768;
        const bool h1 = i1 < kSliceF4, h2 = i2 < kSliceF4, h3 = i3 < kSliceF4;
        float4 a = __ldcs(&b4[i0]);
        float4 b, c, d;
        if (h1) b = __ldcs(&b4[i1]);
        if (h2) c = __ldcs(&b4[i2]);
        if (h3) d = __ldcs(&b4[i3]);
        if (fmax4(a) > T) {
            int g = slice * kSliceF + 4 * i0;
            PUSHK(a.x, g) PUSHK(a.y, g + 1) PUSHK(a.z, g + 2) PUSHK(a.w, g + 3)
        }
        if (h1 && fmax4(b) > T) {
            int g = slice * kSliceF + 4 * i1;
            PUSHK(b.x, g) PUSHK(b.y, g + 1) PUSHK(b.z, g + 2) PUSHK(b.w, g + 3)
        }
        if (h2 && fmax4(c) > T) {
            int g = slice * kSliceF + 4 * i2;
            PUSHK(c.x, g) PUSHK(c.y, g + 1) PUSHK(c.z, g + 2) PUSHK(c.w, g + 3)
        }
        if (h3 && fmax4(d) > T) {
            int g = slice * kSliceF + 4 * i3;
            PUSHK(d.x, g) PUSHK(d.y, g + 1) PUSHK(d.z, g + 2) PUSHK(d.w, g + 3)
        }
    }
#undef PUSHK
    __syncthreads();

    const int raw = s_cnt;
    const int cnt = raw < kSegCap ? raw : kSegCap;
    unsigned long long* seg = &g_cand[((long long)row << 12) + (slice << 9)];
    for (int e = tid; e < cnt; e += 256)
        seg[e] = s_c[e];
    if (tid == 0) g_cnt[sb] = raw;
}

// ---------------------------------------------------------------------------
// Shared descending sort (zero-pads [total, npad)); requires total <= 4096.
// Must be called by all 1024 threads (uniform).
// ---------------------------------------------------------------------------
__device__ void sort_desc(unsigned long long* s_data, int total, int tid) {
    int npad = 64;
    while (npad < total) npad <<= 1;
    for (int i = total + tid; i < npad; i += 1024) s_data[i] = 0ull;
    __syncthreads();

    if (npad <= 1024) {
        const bool act = tid < npad;
        unsigned long long v = act ? s_data[tid] : 0ull;
        for (int k = 2; k <= npad; k <<= 1) {
            int j = k >> 1;
            for (; j >= 32; j >>= 1) {
                __syncthreads();
                if (act) s_data[tid] = v;
                __syncthreads();
                if (act) {
                    unsigned long long u = s_data[tid ^ j];
                    bool takeMax = (((tid & k) == 0) == ((tid & j) == 0));
                    v = takeMax ? (v > u ? v : u) : (v < u ? v : u);
                }
            }
            for (; j > 0; j >>= 1) {
                unsigned long long u = shfl_xor64(v, j);
                bool takeMax = (((tid & k) == 0) == ((tid & j) == 0));
                v = takeMax ? (v > u ? v : u) : (v < u ? v : u);
            }
        }
        __syncthreads();
        if (act) s_data[tid] = v;
        __syncthreads();
    } else {
        for (int k = 2; k <= npad; k <<= 1) {
            for (int j = k >> 1; j > 0; j >>= 1) {
#pragma unroll 1
                for (int i = tid; i < npad; i += 1024) {
                    int p = i ^ j;
                    if (p > i) {
                        unsigned long long a = s_data[i], b = s_data[p];
                        bool desc = ((i & k) == 0);
                        if (desc ? (a < b) : (a > b)) { s_data[i] = b; s_data[p] = a; }
                    }
                }
                __syncthreads();
            }
        }
    }
}

// ---------------------------------------------------------------------------
// K2: per-row gather + validity + sort + top-p + scatter.
// valid (one global threshold): total >= 50 and no slice overflow ==> the
// top-50 values all exceed T and are therefore all in the candidate set.
// ---------------------------------------------------------------------------
__global__ void __launch_bounds__(1024)
sort_scatter_kernel(const float* __restrict__ in, float* __restrict__ out) {
    extern __shared__ __align__(16) unsigned long long s_data[];  // kRowCap
    __shared__ int   s_pref[kSlices];
    __shared__ int   s_cnt8[kSlices];
    __shared__ int   s_total, s_ovf;
    __shared__ float s_wm[32];
    __shared__ int   s_wcnt[32], s_woff[32];
    __shared__ float s_ex[kTopK];
    __shared__ int   s_k;

    const int row = blockIdx.x;
    const int tid = threadIdx.x, lane = tid & 31, wid = tid >> 5;
    const float* rin  = in  + (long long)row * kVocab;
    float*       rout = out + (long long)row * kVocab;

    if (tid < kSlices) s_cnt8[tid] = g_cnt[row * kSlices + tid];
    __syncthreads();
    if (tid == 0) {
        int tot = 0, ovf = 0;
#pragma unroll
        for (int j = 0; j < kSlices; ++j) {
            int c = s_cnt8[j];
            if (c > kSegCap) { ovf = 1; c = kSegCap; }
            s_pref[j] = tot; tot += c;
        }
        s_total = tot; s_ovf = ovf;
    }
    __syncthreads();
    int total = s_total;
    const bool valid = (!s_ovf && total >= kTopK);

    if (valid) {
        if (wid < kSlices) {
            const int c = min(s_cnt8[wid], kSegCap);
            const int off = s_pref[wid];
            const unsigned long long* seg = &g_cand[((long long)row << 12) + (wid << 9)];
            for (int e = lane; e < c; e += 32)
                s_data[off + e] = seg[e];
        }
        __syncthreads();
        sort_desc(s_data, total, tid);
    } else {
        // ---- rare fallback: full-row rescan with sampled threshold ladder ----
        float sv = __ldg(&rin[tid * (kVocab / 1024)]);
#pragma unroll
        for (int o = 16; o > 0; o >>= 1)
            sv = fmaxf(sv, __shfl_xor_sync(0xffffffffu, sv, o));
        if (lane == 0) s_wm[wid] = sv;
        __syncthreads();
        if (wid == 0) {
            float x = s_wm[lane];
#pragma unroll
            for (int k = 2; k <= 32; k <<= 1) {
#pragma unroll
                for (int j = k >> 1; j > 0; j >>= 1) {
                    float y     = __shfl_xor_sync(0xffffffffu, x, j);
                    bool  up    = ((lane & k) == 0);
                    bool  lower = ((lane & j) == 0);
                    x = (up == lower) ? fminf(x, y) : fmaxf(x, y);
                }
            }
            s_wm[lane] = x;  // ascending
        }
        __syncthreads();

        unsigned long long* seg = s_data + 2048;   // per-warp segments region
        const float4* rin4 = reinterpret_cast<const float4*>(rin);
        int rank = 7;
        for (int attempt = 0; attempt < 6; ++attempt) {
            if (tid < 32) s_wcnt[tid] = 0;
            __syncthreads();
            const float T = s_wm[31 - rank];
            for (int i = tid; i < kVocab / 4; i += 1024) {
                float4 a = __ldg(&rin4[i]);
                if (fmax4(a) > T) {
#define FPUSH(val, gi)                                                          \
    if ((val) > T) { int p = atomicAdd(&s_wcnt[wid], 1);                        \
        if (p < kWCap)                                                          \
            seg[wid * kWCap + p] =                                              \
                ((unsigned long long)f2key(val) << 32) | (unsigned)(gi); }
                    FPUSH(a.x, 4 * i) FPUSH(a.y, 4 * i + 1)
                    FPUSH(a.z, 4 * i + 2) FPUSH(a.w, 4 * i + 3)
#undef FPUSH
                }
            }
            __syncthreads();
            if (wid == 0) {
                int c = s_wcnt[lane];
                int ov = __any_sync(0xffffffffu, c > kWCap) ? 1 : 0;
                int t = c;
#pragma unroll
                for (int o = 16; o > 0; o >>= 1) t += __shfl_xor_sync(0xffffffffu, t, o);
                if (lane == 0) { s_total = t; s_ovf = ov; }
            }
            __syncthreads();
            const int tot = s_total, ov = s_ovf;
            if (tot >= kTopK && !ov) break;
            rank = ov ? (rank >> 1) : (rank < 31 ? rank * 2 + 1 : 31);
            __syncthreads();
        }
        // compact per-warp segments into s_data[0..total)
        if (wid == 0) {
            int c = min(s_wcnt[lane], kWCap);
            int x = c;
#pragma unroll
            for (int o = 1; o < 32; o <<= 1) {
                int y = __shfl_up_sync(0xffffffffu, x, o);
                if (lane >= o) x += y;
            }
            s_woff[lane] = x - c;
            if (lane == 31) s_total = x;  // total of capped counts
        }
        __syncthreads();
        {
            const int c = min(s_wcnt[wid], kWCap);
            const int off = s_woff[wid];
            for (int e = lane; e < c; e += 32)
                s_data[off + e] = seg[wid * kWCap + e];
        }
        __syncthreads();
        total = s_total;
        sort_desc(s_data, total, tid);
    }

    // ---------------- top-p epilogue ----------------
    const int lim = (total < kTopK) ? total : kTopK;
    if (wid == 0) {
        float m = key2f((unsigned)(s_data[0] >> 32));
#pragma unroll
        for (int j = lane; j < kTopK; j += 32)
            if (j < lim)
                s_ex[j] = expf(key2f((unsigned)(s_data[j] >> 32)) - m);
    }
    __syncthreads();
    if (tid == 0) {
        int kk = 0;
        if (lim > 0) {
            float Z = 0.f;
            for (int j = 0; j < lim; ++j) Z += s_ex[j];
            const float invZ = 1.0f / Z;
            float cum = 0.f;
            for (int j = 0; j < lim; ++j) {
                if (j > 0 && cum > kTopP) break;
                kk = j + 1;
                cum += s_ex[j] * invZ;
            }
        }
        s_k = kk;
    }
    __syncthreads();

    if (tid < s_k) {
        unsigned long long c = s_data[tid];
        rout[(int)(c & 0xFFFFFFFFu)] = key2f((unsigned)(c >> 32));
    }
}

extern "C" void kernel_launch(void* const* d_in, const int* in_sizes, int n_in,
                              void* d_out, int out_size) {
    const float* in = (const float*)d_in[0];
    float* out = (float*)d_out;
    int rows = in_sizes[0] / kVocab;
    stream_kernel<<<kFillBlocks + rows * kSlices, 256>>>(in, out, rows);
    sort_scatter_kernel<<<rows, 1024, kRowCap * sizeof(unsigned long long)>>>(in, out);
}

// round 12
// speedup vs baseline: 2.1884x; 1.0846x over previous
#include <cuda_runtime.h>
#include <cstdint>

static constexpr int   kVocab   = 128000;
static constexpr int   kTopK    = 50;
static constexpr float kTopP    = 0.9f;
static constexpr float kNeg     = -1000000000.0f;
static constexpr float kFixedT  = 3.0f;   // guess for N(0,1) logits; verified in K2
static constexpr int   kMaxRows = 256;
static constexpr int   kSlices  = 8;
static constexpr int   kSliceF  = kVocab / kSlices;   // 16000 floats per scan block
static constexpr int   kSliceF4 = kSliceF / 4;        // 4000 float4
static constexpr int   kSegCap  = 512;                // per-slice candidate cap
static constexpr int   kRowCap  = kSlices * kSegCap;  // 4096 (also smem sort area)
static constexpr int   kFillBlocks = 2048;
static constexpr int   kNT2     = 256;                // K2 threads
static constexpr int   kFWCap   = 256;                // fallback per-warp cap (8 warps)

// Global scratch (device globals — no allocation).
__device__ unsigned long long g_cand[kMaxRows * kRowCap];   // 8 MB
__device__ int g_cnt[kMaxRows * kSlices];

// Order-preserving float -> uint32 key (monotone increasing, >0 for any float).
__device__ __forceinline__ unsigned f2key(float f) {
    unsigned b = __float_as_uint(f);
    return (b & 0x80000000u) ? ~b : (b | 0x80000000u);
}
__device__ __forceinline__ float key2f(unsigned k) {
    unsigned b = (k & 0x80000000u) ? (k & 0x7FFFFFFFu) : ~k;
    return __uint_as_float(b);
}
__device__ __forceinline__ unsigned long long shfl_xor64(unsigned long long v, int j) {
    unsigned lo = __shfl_xor_sync(0xffffffffu, (unsigned)v, j);
    unsigned hi = __shfl_xor_sync(0xffffffffu, (unsigned)(v >> 32), j);
    return ((unsigned long long)hi << 32) | lo;
}
__device__ __forceinline__ float fmax4(float4 a) {
    return fmaxf(fmaxf(a.x, a.y), fmaxf(a.z, a.w));
}

// ---------------------------------------------------------------------------
// K1: fill blocks (0..2047) NEG-fill output; scan blocks (2048..) stream one
// 16000-float slice each with the fixed threshold.  (UNCHANGED from R11.)
// ---------------------------------------------------------------------------
__global__ void __launch_bounds__(256)
stream_kernel(const float* __restrict__ in, float* __restrict__ out, int rows) {
    const int tid = threadIdx.x;

    if (blockIdx.x < kFillBlocks) {
        float4* out4 = reinterpret_cast<float4*>(out);
        const int n4 = rows * (kVocab / 4);
        const float4 neg4 = make_float4(kNeg, kNeg, kNeg, kNeg);
        const int stride = kFillBlocks * 256;
        int i = blockIdx.x * 256 + tid;
#pragma unroll 4
        for (; i < n4; i += stride)
            __stcs(&out4[i], neg4);
        return;
    }

    const int sb    = blockIdx.x - kFillBlocks;   // 0 .. rows*8-1
    const int row   = sb >> 3;
    const int slice = sb & 7;
    const float* base = in + (long long)row * kVocab + slice * kSliceF;

    __shared__ int s_cnt;
    __shared__ unsigned long long s_c[kSegCap];
    if (tid == 0) s_cnt = 0;
    __syncthreads();
    const float T = kFixedT;

#define PUSHK(val, gi)                                                         \
    if ((val) > T) { int p = atomicAdd(&s_cnt, 1);                             \
        if (p < kSegCap)                                                       \
            s_c[p] = ((unsigned long long)f2key(val) << 32) | (unsigned)(gi); }

    const float4* b4 = reinterpret_cast<const float4*>(base);
    for (int i0 = tid; i0 < kSliceF4; i0 += 1024) {
        const int i1 = i0 + 256, i2 = i0 + 512, i3 = i0 + 768;
        const bool h1 = i1 < kSliceF4, h2 = i2 < kSliceF4, h3 = i3 < kSliceF4;
        float4 a = __ldcs(&b4[i0]);
        float4 b, c, d;
        if (h1) b = __ldcs(&b4[i1]);
        if (h2) c = __ldcs(&b4[i2]);
        if (h3) d = __ldcs(&b4[i3]);
        if (fmax4(a) > T) {
            int g = slice * kSliceF + 4 * i0;
            PUSHK(a.x, g) PUSHK(a.y, g + 1) PUSHK(a.z, g + 2) PUSHK(a.w, g + 3)
        }
        if (h1 && fmax4(b) > T) {
            int g = slice * kSliceF + 4 * i1;
            PUSHK(b.x, g) PUSHK(b.y, g + 1) PUSHK(b.z, g + 2) PUSHK(b.w, g + 3)
        }
        if (h2 && fmax4(c) > T) {
            int g = slice * kSliceF + 4 * i2;
            PUSHK(c.x, g) PUSHK(c.y, g + 1) PUSHK(c.z, g + 2) PUSHK(c.w, g + 3)
        }
        if (h3 && fmax4(d) > T) {
            int g = slice * kSliceF + 4 * i3;
            PUSHK(d.x, g) PUSHK(d.y, g + 1) PUSHK(d.z, g + 2) PUSHK(d.w, g + 3)
        }
    }
#undef PUSHK
    __syncthreads();

    const int raw = s_cnt;
    const int cnt = raw < kSegCap ? raw : kSegCap;
    unsigned long long* seg = &g_cand[((long long)row << 12) + (slice << 9)];
    for (int e = tid; e < cnt; e += 256)
        seg[e] = s_c[e];
    if (tid == 0) g_cnt[sb] = raw;
}

// ---------------------------------------------------------------------------
// Shared descending sort for kNT2=256 threads; zero-pads [total, npad).
// Register-hybrid when npad <= 256; strided shared loop otherwise (<= 4096).
// ---------------------------------------------------------------------------
__device__ void sort_desc256(unsigned long long* s_data, int total, int tid) {
    int npad = 64;
    while (npad < total) npad <<= 1;
    for (int i = total + tid; i < npad; i += kNT2) s_data[i] = 0ull;
    __syncthreads();

    if (npad <= kNT2) {
        const bool act = tid < npad;
        unsigned long long v = act ? s_data[tid] : 0ull;
        for (int k = 2; k <= npad; k <<= 1) {
            int j = k >> 1;
            for (; j >= 32; j >>= 1) {
                __syncthreads();
                if (act) s_data[tid] = v;
                __syncthreads();
                if (act) {
                    unsigned long long u = s_data[tid ^ j];
                    bool takeMax = (((tid & k) == 0) == ((tid & j) == 0));
                    v = takeMax ? (v > u ? v : u) : (v < u ? v : u);
                }
            }
            for (; j > 0; j >>= 1) {
                unsigned long long u = shfl_xor64(v, j);
                bool takeMax = (((tid & k) == 0) == ((tid & j) == 0));
                v = takeMax ? (v > u ? v : u) : (v < u ? v : u);
            }
        }
        __syncthreads();
        if (act) s_data[tid] = v;
        __syncthreads();
    } else {
        for (int k = 2; k <= npad; k <<= 1) {
            for (int j = k >> 1; j > 0; j >>= 1) {
#pragma unroll 1
                for (int i = tid; i < npad; i += kNT2) {
                    int p = i ^ j;
                    if (p > i) {
                        unsigned long long a = s_data[i], b = s_data[p];
                        bool desc = ((i & k) == 0);
                        if (desc ? (a < b) : (a > b)) { s_data[i] = b; s_data[p] = a; }
                    }
                }
                __syncthreads();
            }
        }
    }
}

// ---------------------------------------------------------------------------
// K2 (256 threads): per-row gather + validity + sort + top-p + scatter.
// valid: total >= 50 and no slice overflow ==> top-50 captured (one threshold).
// ---------------------------------------------------------------------------
__global__ void __launch_bounds__(kNT2)
sort_scatter_kernel(const float* __restrict__ in, float* __restrict__ out) {
    extern __shared__ __align__(16) unsigned long long s_data[];  // kRowCap
    __shared__ int   s_pref[kSlices];
    __shared__ int   s_cnt8[kSlices];
    __shared__ int   s_total, s_ovf;
    __shared__ float s_wm[32];
    __shared__ int   s_wcnt[8], s_woff[8];
    __shared__ float s_ex[kTopK];
    __shared__ int   s_k;

    const int row = blockIdx.x;
    const int tid = threadIdx.x, lane = tid & 31, wid = tid >> 5;  // 8 warps
    const float* rin  = in  + (long long)row * kVocab;
    float*       rout = out + (long long)row * kVocab;

    if (tid < kSlices) s_cnt8[tid] = g_cnt[row * kSlices + tid];
    __syncthreads();
    if (tid == 0) {
        int tot = 0, ovf = 0;
#pragma unroll
        for (int j = 0; j < kSlices; ++j) {
            int c = s_cnt8[j];
            if (c > kSegCap) { ovf = 1; c = kSegCap; }
            s_pref[j] = tot; tot += c;
        }
        s_total = tot; s_ovf = ovf;
    }
    __syncthreads();
    int total = s_total;
    const bool valid = (!s_ovf && total >= kTopK);

    if (valid) {
        // One warp per slice (8 warps = 8 slices).
        {
            const int c = min(s_cnt8[wid], kSegCap);
            const int off = s_pref[wid];
            const unsigned long long* seg = &g_cand[((long long)row << 12) + (wid << 9)];
            for (int e = lane; e < c; e += 32)
                s_data[off + e] = seg[e];
        }
        __syncthreads();
        sort_desc256(s_data, total, tid);
    } else {
        // ---- rare fallback: full-row rescan with sampled threshold ladder ----
        // 1024 samples: 4 per thread; 32 group-maxes (32 samples each), same
        // statistics as the original 1024-thread sampler.
        const int step = kVocab / 1024;
#pragma unroll
        for (int r = 0; r < 4; ++r) {
            float sv = __ldg(&rin[(r * kNT2 + tid) * step]);
#pragma unroll
            for (int o = 16; o > 0; o >>= 1)
                sv = fmaxf(sv, __shfl_xor_sync(0xffffffffu, sv, o));
            if (lane == 0) s_wm[r * 8 + wid] = sv;
        }
        __syncthreads();
        if (wid == 0) {
            float x = s_wm[lane];
#pragma unroll
            for (int k = 2; k <= 32; k <<= 1) {
#pragma unroll
                for (int j = k >> 1; j > 0; j >>= 1) {
                    float y     = __shfl_xor_sync(0xffffffffu, x, j);
                    bool  up    = ((lane & k) == 0);
                    bool  lower = ((lane & j) == 0);
                    x = (up == lower) ? fminf(x, y) : fmaxf(x, y);
                }
            }
            s_wm[lane] = x;  // ascending
        }
        __syncthreads();

        unsigned long long* seg = s_data + 2048;   // 8 warps x 256 slots
        const float4* rin4 = reinterpret_cast<const float4*>(rin);
        int rank = 7;
        for (int attempt = 0; attempt < 6; ++attempt) {
            if (tid < 8) s_wcnt[tid] = 0;
            __syncthreads();
            const float T = s_wm[31 - rank];
            for (int i = tid; i < kVocab / 4; i += kNT2) {
                float4 a = __ldg(&rin4[i]);
                if (fmax4(a) > T) {
#define FPUSH(val, gi)                                                          \
    if ((val) > T) { int p = atomicAdd(&s_wcnt[wid], 1);                        \
        if (p < kFWCap)                                                         \
            seg[wid * kFWCap + p] =                                             \
                ((unsigned long long)f2key(val) << 32) | (unsigned)(gi); }
                    FPUSH(a.x, 4 * i) FPUSH(a.y, 4 * i + 1)
                    FPUSH(a.z, 4 * i + 2) FPUSH(a.w, 4 * i + 3)
#undef FPUSH
                }
            }
            __syncthreads();
            if (tid == 0) {
                int t = 0, ov = 0;
#pragma unroll
                for (int j = 0; j < 8; ++j) {
                    int c = s_wcnt[j];
                    if (c > kFWCap) ov = 1;
                    t += min(c, kFWCap);
                }
                s_total = t; s_ovf = ov;
            }
            __syncthreads();
            const int tot = s_total, ov = s_ovf;
            if (tot >= kTopK && !ov) break;
            rank = ov ? (rank >> 1) : (rank < 31 ? rank * 2 + 1 : 31);
            __syncthreads();
        }
        // compact 8 per-warp segments into s_data[0..total)
        if (tid == 0) {
            int off = 0;
#pragma unroll
            for (int j = 0; j < 8; ++j) {
                s_woff[j] = off;
                off += min(s_wcnt[j], kFWCap);
            }
            s_total = off;
        }
        __syncthreads();
        {
            const int c = min(s_wcnt[wid], kFWCap);
            const int off = s_woff[wid];
            for (int e = lane; e < c; e += 32)
                s_data[off + e] = seg[wid * kFWCap + e];
        }
        __syncthreads();
        total = s_total;
        sort_desc256(s_data, total, tid);
    }

    // ---------------- top-p epilogue ----------------
    const int lim = (total < kTopK) ? total : kTopK;
    if (wid == 0) {
        float m = key2f((unsigned)(s_data[0] >> 32));
#pragma unroll
        for (int j = lane; j < kTopK; j += 32)
            if (j < lim)
                s_ex[j] = expf(key2f((unsigned)(s_data[j] >> 32)) - m);
    }
    __syncthreads();
    if (tid == 0) {
        int kk = 0;
        if (lim > 0) {
            float Z = 0.f;
            for (int j = 0; j < lim; ++j) Z += s_ex[j];
            const float invZ = 1.0f / Z;
            float cum = 0.f;
            for (int j = 0; j < lim; ++j) {
                if (j > 0 && cum > kTopP) break;
                kk = j + 1;
                cum += s_ex[j] * invZ;
            }
        }
        s_k = kk;
    }
    __syncthreads();

    if (tid < s_k) {
        unsigned long long c = s_data[tid];
        rout[(int)(c & 0xFFFFFFFFu)] = key2f((unsigned)(c >> 32));
    }
}

extern "C" void kernel_launch(void* const* d_in, const int* in_sizes, int n_in,
                              void* d_out, int out_size) {
    const float* in = (const float*)d_in[0];
    float* out = (float*)d_out;
    int rows = in_sizes[0] / kVocab;
    stream_kernel<<<kFillBlocks + rows * kSlices, 256>>>(in, out, rows);
    cudaFuncSetAttribute(sort_scatter_kernel,
                         cudaFuncAttributeMaxDynamicSharedMemorySize,
                         kRowCap * (int)sizeof(unsigned long long));
    sort_scatter_kernel<<<rows, kNT2, kRowCap * sizeof(unsigned long long)>>>(in, out);
}

// round 13
// speedup vs baseline: 2.2245x; 1.0165x over previous
#include <cuda_runtime.h>
#include <cstdint>

static constexpr int   kVocab   = 128000;
static constexpr int   kTopK    = 50;
static constexpr float kTopP    = 0.9f;
static constexpr float kNeg     = -1000000000.0f;
static constexpr float kFixedT  = 3.0f;   // verified per-row; fallback if wrong
static constexpr int   kMaxRows = 256;
static constexpr int   kSlices  = 8;
static constexpr int   kSliceF  = kVocab / kSlices;   // 16000 floats per block
static constexpr int   kSliceF4 = kSliceF / 4;        // 4000 float4
static constexpr int   kSegCap  = 512;                // per-slice AND row-total cap
static constexpr int   kFWCap   = 64;                 // fallback per-warp cap

// Global scratch (device globals — no allocation).
__device__ unsigned long long g_cand[kMaxRows * kSlices * kSegCap];  // 8 MB
__device__ int g_cnt[kMaxRows * kSlices];
__device__ unsigned g_done[kMaxRows];   // monotone across graph replays

// Order-preserving float -> uint32 key (monotone increasing, >0 for any float).
__device__ __forceinline__ unsigned f2key(float f) {
    unsigned b = __float_as_uint(f);
    return (b & 0x80000000u) ? ~b : (b | 0x80000000u);
}
__device__ __forceinline__ float key2f(unsigned k) {
    unsigned b = (k & 0x80000000u) ? (k & 0x7FFFFFFFu) : ~k;
    return __uint_as_float(b);
}
__device__ __forceinline__ unsigned long long shfl_xor64(unsigned long long v, int j) {
    unsigned lo = __shfl_xor_sync(0xffffffffu, (unsigned)v, j);
    unsigned hi = __shfl_xor_sync(0xffffffffu, (unsigned)(v >> 32), j);
    return ((unsigned long long)hi << 32) | lo;
}
__device__ __forceinline__ float fmax4(float4 a) {
    return fmaxf(fmaxf(a.x, a.y), fmaxf(a.z, a.w));
}

// Descending bitonic sort over s_data[0..total) padded to npad (<=512), 256 thr.
__device__ void sort_desc256(unsigned long long* s_data, int total, int tid) {
    int npad = 64;
    while (npad < total) npad <<= 1;
    for (int i = total + tid; i < npad; i += 256) s_data[i] = 0ull;
    __syncthreads();

    if (npad <= 256) {
        const bool act = tid < npad;
        unsigned long long v = act ? s_data[tid] : 0ull;
        for (int k = 2; k <= npad; k <<= 1) {
            int j = k >> 1;
            for (; j >= 32; j >>= 1) {
                __syncthreads();
                if (act) s_data[tid] = v;
                __syncthreads();
                if (act) {
                    unsigned long long u = s_data[tid ^ j];
                    bool takeMax = (((tid & k) == 0) == ((tid & j) == 0));
                    v = takeMax ? (v > u ? v : u) : (v < u ? v : u);
                }
            }
            for (; j > 0; j >>= 1) {
                unsigned long long u = shfl_xor64(v, j);
                bool takeMax = (((tid & k) == 0) == ((tid & j) == 0));
                v = takeMax ? (v > u ? v : u) : (v < u ? v : u);
            }
        }
        __syncthreads();
        if (act) s_data[tid] = v;
        __syncthreads();
    } else {  // npad == 512
        for (int k = 2; k <= npad; k <<= 1) {
            for (int j = k >> 1; j > 0; j >>= 1) {
#pragma unroll 1
                for (int i = tid; i < npad; i += 256) {
                    int p = i ^ j;
                    if (p > i) {
                        unsigned long long a = s_data[i], b = s_data[p];
                        bool desc = ((i & k) == 0);
                        if (desc ? (a < b) : (a > b)) { s_data[i] = b; s_data[p] = a; }
                    }
                }
                __syncthreads();
            }
        }
    }
}

// ---------------------------------------------------------------------------
// Fused kernel: rows*8 blocks of 256 threads. Each block streams one slice
// (read + NEG-fill + candidate select); the 8th finisher of each row sorts,
// applies top-p, and scatters.
// ---------------------------------------------------------------------------
__global__ void __launch_bounds__(256)
fused_kernel(const float* __restrict__ in, float* __restrict__ out) {
    __shared__ unsigned long long s_c[kSegCap];     // stage -> gather/sort area
    __shared__ unsigned long long s_seg[kSegCap];   // fallback ladder segments
    __shared__ int   s_cnt;
    __shared__ int   s_cnt8[kSlices], s_pref[kSlices];
    __shared__ int   s_total, s_ovf, s_k, s_last;
    __shared__ int   s_wcnt[8];
    __shared__ float s_wm[32];
    __shared__ float s_ex[kTopK];

    const int sb    = blockIdx.x;
    const int row   = sb >> 3;
    const int slice = sb & 7;
    const int tid   = threadIdx.x, lane = tid & 31, wid = tid >> 5;
    const float* rin  = in  + (long long)row * kVocab;
    float*       rout = out + (long long)row * kVocab;
    const float* base = rin + slice * kSliceF;
    float4*      o4   = reinterpret_cast<float4*>(rout + slice * kSliceF);

    if (tid == 0) s_cnt = 0;
    __syncthreads();
    const float T = kFixedT;

    // ---------------- Phase 1: fused read + NEG-fill + select ----------------
#define PUSHK(val, gi)                                                         \
    if ((val) > T) { int p = atomicAdd(&s_cnt, 1);                             \
        if (p < kSegCap)                                                       \
            s_c[p] = ((unsigned long long)f2key(val) << 32) | (unsigned)(gi); }

    const float4* b4 = reinterpret_cast<const float4*>(base);
    const float4 neg4 = make_float4(kNeg, kNeg, kNeg, kNeg);
    for (int i0 = tid; i0 < kSliceF4; i0 += 1024) {
        const int i1 = i0 + 256, i2 = i0 + 512, i3 = i0 + 768;
        const bool h1 = i1 < kSliceF4, h2 = i2 < kSliceF4, h3 = i3 < kSliceF4;
        float4 a = __ldcs(&b4[i0]);
        float4 b, c, d;
        if (h1) b = __ldcs(&b4[i1]);
        if (h2) c = __ldcs(&b4[i2]);
        if (h3) d = __ldcs(&b4[i3]);
        __stcs(&o4[i0], neg4);
        if (h1) __stcs(&o4[i1], neg4);
        if (h2) __stcs(&o4[i2], neg4);
        if (h3) __stcs(&o4[i3], neg4);
        if (fmax4(a) > T) {
            int g = slice * kSliceF + 4 * i0;
            PUSHK(a.x, g) PUSHK(a.y, g + 1) PUSHK(a.z, g + 2) PUSHK(a.w, g + 3)
        }
        if (h1 && fmax4(b) > T) {
            int g = slice * kSliceF + 4 * i1;
            PUSHK(b.x, g) PUSHK(b.y, g + 1) PUSHK(b.z, g + 2) PUSHK(b.w, g + 3)
        }
        if (h2 && fmax4(c) > T) {
            int g = slice * kSliceF + 4 * i2;
            PUSHK(c.x, g) PUSHK(c.y, g + 1) PUSHK(c.z, g + 2) PUSHK(c.w, g + 3)
        }
        if (h3 && fmax4(d) > T) {
            int g = slice * kSliceF + 4 * i3;
            PUSHK(d.x, g) PUSHK(d.y, g + 1) PUSHK(d.z, g + 2) PUSHK(d.w, g + 3)
        }
    }
#undef PUSHK
    __syncthreads();

    // Publish segment + count, then signal completion of this slice.
    const int raw = s_cnt;
    const int cnt = raw < kSegCap ? raw : kSegCap;
    unsigned long long* seg = &g_cand[((long long)row * kSlices + slice) * kSegCap];
    for (int e = tid; e < cnt; e += 256)
        seg[e] = s_c[e];
    if (tid == 0) g_cnt[row * kSlices + slice] = raw;
    __threadfence();
    __syncthreads();
    if (tid == 0) {
        unsigned old = atomicAdd(&g_done[row], 1u);
        s_last = ((old & 7u) == 7u) ? 1 : 0;   // monotone counter: 8th arrival this run
    }
    __syncthreads();
    if (!s_last) return;
    __threadfence();   // acquire: other blocks' seg/cnt/NEG writes now visible

    // ---------------- Phase 2 (one block per row): gather + sort ----------------
    if (tid < kSlices) s_cnt8[tid] = g_cnt[row * kSlices + tid];
    __syncthreads();
    if (tid == 0) {
        int tot = 0, ovf = 0;
#pragma unroll
        for (int j = 0; j < kSlices; ++j) {
            int c = s_cnt8[j];
            if (c > kSegCap) { ovf = 1; c = kSegCap; }
            s_pref[j] = tot; tot += c;
        }
        s_total = tot; s_ovf = (ovf || tot > kSegCap) ? 1 : 0;
    }
    __syncthreads();
    int total = s_total;
    const bool valid = (!s_ovf && total >= kTopK);

    if (valid) {
        // One warp per slice gathers into s_c (overwrites stage data).
        {
            const int c = min(s_cnt8[wid], kSegCap);
            const int off = s_pref[wid];
            const unsigned long long* sseg =
                &g_cand[((long long)row * kSlices + wid) * kSegCap];
            for (int e = lane; e < c; e += 32)
                s_c[off + e] = sseg[e];
        }
        __syncthreads();
        sort_desc256(s_c, total, tid);
    } else {
        // ---- rare fallback: rescan full row with sampled threshold ladder ----
        const int step = kVocab / 1024;
#pragma unroll
        for (int r = 0; r < 4; ++r) {
            float sv = __ldg(&rin[(r * 256 + tid) * step]);
#pragma unroll
            for (int o = 16; o > 0; o >>= 1)
                sv = fmaxf(sv, __shfl_xor_sync(0xffffffffu, sv, o));
            if (lane == 0) s_wm[r * 8 + wid] = sv;
        }
        __syncthreads();
        if (wid == 0) {
            float x = s_wm[lane];
#pragma unroll
            for (int k = 2; k <= 32; k <<= 1) {
#pragma unroll
                for (int j = k >> 1; j > 0; j >>= 1) {
                    float y     = __shfl_xor_sync(0xffffffffu, x, j);
                    bool  up    = ((lane & k) == 0);
                    bool  lower = ((lane & j) == 0);
                    x = (up == lower) ? fminf(x, y) : fmaxf(x, y);
                }
            }
            s_wm[lane] = x;  // ascending
        }
        __syncthreads();

        const float4* rin4 = reinterpret_cast<const float4*>(rin);
        int rank = 2;   // expected ~375 exceedances; ladder adjusts both ways
        for (int attempt = 0; attempt < 6; ++attempt) {
            if (tid < 8) s_wcnt[tid] = 0;
            __syncthreads();
            const float Tf = s_wm[31 - rank];
            for (int i = tid; i < kVocab / 4; i += 256) {
                float4 a = __ldg(&rin4[i]);
                if (fmax4(a) > Tf) {
#define FPUSH(val, gi)                                                          \
    if ((val) > Tf) { int p = atomicAdd(&s_wcnt[wid], 1);                       \
        if (p < kFWCap)                                                         \
            s_seg[wid * kFWCap + p] =                                           \
                ((unsigned long long)f2key(val) << 32) | (unsigned)(gi); }
                    FPUSH(a.x, 4 * i) FPUSH(a.y, 4 * i + 1)
                    FPUSH(a.z, 4 * i + 2) FPUSH(a.w, 4 * i + 3)
#undef FPUSH
                }
            }
            __syncthreads();
            if (tid == 0) {
                int t = 0, ov = 0;
#pragma unroll
                for (int j = 0; j < 8; ++j) {
                    int c = s_wcnt[j];
                    if (c > kFWCap) ov = 1;
                    t += min(c, kFWCap);
                }
                s_total = t; s_ovf = ov;
            }
            __syncthreads();
            const int tot = s_total, ov = s_ovf;
            if (tot >= kTopK && !ov) break;
            rank = ov ? (rank >> 1) : (rank < 31 ? rank * 2 + 1 : 31);
            __syncthreads();
        }
        // compact per-warp segments into s_c[0..total)
        if (tid == 0) {
            int off = 0;
#pragma unroll
            for (int j = 0; j < 8; ++j) {
                s_pref[j] = off;
                off += min(s_wcnt[j], kFWCap);
            }
            s_total = off;
        }
        __syncthreads();
        {
            const int c = min(s_wcnt[wid], kFWCap);
            const int off = s_pref[wid];
            for (int e = lane; e < c; e += 32)
                s_c[off + e] = s_seg[wid * kFWCap + e];
        }
        __syncthreads();
        total = s_total;
        sort_desc256(s_c, total, tid);
    }

    // ---------------- Phase 3: top-p epilogue + scatter ----------------
    const int lim = (total < kTopK) ? total : kTopK;
    if (wid == 0) {
        float m = key2f((unsigned)(s_c[0] >> 32));
#pragma unroll
        for (int j = lane; j < kTopK; j += 32)
            if (j < lim)
                s_ex[j] = expf(key2f((unsigned)(s_c[j] >> 32)) - m);
    }
    __syncthreads();
    if (tid == 0) {
        int kk = 0;
        if (lim > 0) {
            float Z = 0.f;
            for (int j = 0; j < lim; ++j) Z += s_ex[j];
            const float invZ = 1.0f / Z;
            float cum = 0.f;
            for (int j = 0; j < lim; ++j) {
                if (j > 0 && cum > kTopP) break;
                kk = j + 1;
                cum += s_ex[j] * invZ;
            }
        }
        s_k = kk;
    }
    __syncthreads();

    if (tid < s_k) {
        unsigned long long c = s_c[tid];
        rout[(int)(c & 0xFFFFFFFFu)] = key2f((unsigned)(c >> 32));
    }
}

extern "C" void kernel_launch(void* const* d_in, const int* in_sizes, int n_in,
                              void* d_out, int out_size) {
    const float* in = (const float*)d_in[0];
    float* out = (float*)d_out;
    int rows = in_sizes[0] / kVocab;
    fused_kernel<<<rows * kSlices, 256>>>(in, out);
}